// round 10
// baseline (speedup 1.0000x reference)
#include <cuda_runtime.h>
#include <cuda_fp16.h>
#include <cstdint>
#include <math.h>

#define SEQ   4096
#define EMB   768
#define HEADS 12
#define HD    64

// ---------------- scratch (static device globals, no runtime alloc) ----------------
__device__ __half g_X[SEQ * EMB];
__device__ __half g_W[4][EMB * EMB];
__device__ __half g_Q[SEQ * EMB];
__device__ __half g_K[SEQ * EMB];
__device__ __half g_V[SEQ * EMB];
__device__ __half g_CTX[SEQ * EMB];
// split-KV partials: [head][qt(32)][chunk(4)] -> O 128x64 fp16, l 128 fp32
__device__ __half g_OP[HEADS * 32 * 4 * 128 * 64];
__device__ float  g_LP[HEADS * 32 * 4 * 128];

// ======================= helpers =======================
__device__ __forceinline__ void mma_f16(float* d, const uint32_t* a, const uint32_t* b) {
    asm volatile(
        "mma.sync.aligned.m16n8k16.row.col.f32.f16.f16.f32 "
        "{%0,%1,%2,%3}, {%4,%5,%6,%7}, {%8,%9}, {%0,%1,%2,%3};"
        : "+f"(d[0]), "+f"(d[1]), "+f"(d[2]), "+f"(d[3])
        : "r"(a[0]), "r"(a[1]), "r"(a[2]), "r"(a[3]), "r"(b[0]), "r"(b[1]));
}
__device__ __forceinline__ void ldsm4(uint32_t* r, uint32_t a) {
    asm volatile("ldmatrix.sync.aligned.m8n8.x4.shared.b16 {%0,%1,%2,%3}, [%4];"
        : "=r"(r[0]), "=r"(r[1]), "=r"(r[2]), "=r"(r[3]) : "r"(a));
}
__device__ __forceinline__ void ldsm4t(uint32_t* r, uint32_t a) {
    asm volatile("ldmatrix.sync.aligned.m8n8.x4.trans.shared.b16 {%0,%1,%2,%3}, [%4];"
        : "=r"(r[0]), "=r"(r[1]), "=r"(r[2]), "=r"(r[3]) : "r"(a));
}
__device__ __forceinline__ uint32_t ex2h2(float x, float y) {
    __half2 h = __floats2half2_rn(x, y);
    uint32_t u = *(uint32_t*)&h, r;
    asm("ex2.approx.f16x2 %0, %1;" : "=r"(r) : "r"(u));
    return r;
}
__device__ __forceinline__ uint32_t smem_u32(const void* p) {
    uint32_t a;
    asm("{ .reg .u64 t; cvta.to.shared.u64 t, %1; cvt.u32.u64 %0, t; }" : "=r"(a) : "l"(p));
    return a;
}
__device__ __forceinline__ void cpa16(uint32_t dst, const void* src) {
    asm volatile("cp.async.cg.shared.global [%0], [%1], 16;" :: "r"(dst), "l"(src));
}
#define CP_COMMIT() asm volatile("cp.async.commit_group;" ::: "memory")
#define CP_WAIT(n)  asm volatile("cp.async.wait_group %0;" :: "n"(n) : "memory")

// ---------------- fp32 -> fp16 converts ----------------
__global__ __launch_bounds__(256) void f2h_kernel(const float* __restrict__ in,
                                                  __half* __restrict__ out) {
    const int i = (blockIdx.x * 256 + threadIdx.x) * 8;
    float4 a = *(const float4*)(in + i);
    float4 b = *(const float4*)(in + i + 4);
    __half2 h[4] = { __floats2half2_rn(a.x, a.y), __floats2half2_rn(a.z, a.w),
                     __floats2half2_rn(b.x, b.y), __floats2half2_rn(b.z, b.w) };
    *(uint4*)(out + i) = *(uint4*)h;
}
__global__ __launch_bounds__(256) void f2h_w4(const float* __restrict__ w0,
                                              const float* __restrict__ w1,
                                              const float* __restrict__ w2,
                                              const float* __restrict__ w3,
                                              __half* __restrict__ out) {
    const int y = blockIdx.y;
    const float* in = y == 0 ? w0 : (y == 1 ? w1 : (y == 2 ? w2 : w3));
    const int i = (blockIdx.x * 256 + threadIdx.x) * 8;
    float4 a = *(const float4*)(in + i);
    float4 b = *(const float4*)(in + i + 4);
    __half2 h[4] = { __floats2half2_rn(a.x, a.y), __floats2half2_rn(a.z, a.w),
                     __floats2half2_rn(b.x, b.y), __floats2half2_rn(b.z, b.w) };
    *(uint4*)(out + (size_t)y * EMB * EMB + i) = *(uint4*)h;
}

// ---------------- fp16 GEMM (R7-validated) ----------------
#define BK2 32
#define NKT2 (EMB / BK2)
#define STG2 4
#define A_ST 80
#define B_ST 272
#define A_TB (128 * A_ST)
#define B_TB (32 * B_ST)
#define GEMM_SMEM (STG2 * (A_TB + B_TB))

template <typename OutT>
__global__ __launch_bounds__(256, 2) void gemm_h(const __half* __restrict__ A,
                                                 const __half* __restrict__ B0,
                                                 const __half* __restrict__ B1,
                                                 const __half* __restrict__ B2,
                                                 const float* __restrict__ bias0,
                                                 const float* __restrict__ bias1,
                                                 const float* __restrict__ bias2,
                                                 OutT* __restrict__ C0,
                                                 OutT* __restrict__ C1,
                                                 OutT* __restrict__ C2,
                                                 float sc0, float sc1, float sc2) {
    extern __shared__ char gsm[];
    const uint32_t sA = smem_u32(gsm);
    const uint32_t sB = sA + STG2 * A_TB;

    const int z = blockIdx.z;
    const __half* B   = z == 0 ? B0 : (z == 1 ? B1 : B2);
    const float* bias = z == 0 ? bias0 : (z == 1 ? bias1 : bias2);
    OutT* C           = z == 0 ? C0 : (z == 1 ? C1 : C2);
    const float scl   = z == 0 ? sc0 : (z == 1 ? sc1 : sc2);

    const int tid  = threadIdx.x;
    const int wid  = tid >> 5;
    const int lane = tid & 31;
    const int l16  = lane & 15;
    const int lh   = lane >> 4;
    const int wm   = (wid >> 2) * 64;
    const int wn   = (wid & 3) * 32;
    const int m0   = blockIdx.y * 128;
    const int n0   = blockIdx.x * 128;

    auto issue = [&](int kt) {
        const int st = kt & 3;
#pragma unroll
        for (int i = 0; i < 2; ++i) {
            int f = i * 256 + tid;
            int row = f >> 2, c = f & 3;
            cpa16(sA + st * A_TB + row * A_ST + c * 16,
                  A + (size_t)(m0 + row) * EMB + kt * BK2 + c * 8);
        }
#pragma unroll
        for (int i = 0; i < 2; ++i) {
            int f = i * 256 + tid;
            int row = f >> 4, c = f & 15;
            cpa16(sB + st * B_TB + row * B_ST + c * 16,
                  B + (size_t)(kt * BK2 + row) * EMB + n0 + c * 8);
        }
        CP_COMMIT();
    };

    float acc[4][4][4];
#pragma unroll
    for (int i = 0; i < 4; ++i)
#pragma unroll
        for (int j = 0; j < 4; ++j)
#pragma unroll
            for (int k = 0; k < 4; ++k) acc[i][j][k] = 0.f;

    issue(0); issue(1); issue(2);

#pragma unroll 1
    for (int kt = 0; kt < NKT2; ++kt) {
        CP_WAIT(2);
        __syncthreads();
        if (kt + 3 < NKT2) issue(kt + 3);
        else CP_COMMIT();

        const uint32_t aS = sA + (kt & 3) * A_TB;
        const uint32_t bS = sB + (kt & 3) * B_TB;

#pragma unroll
        for (int s = 0; s < 2; ++s) {
            uint32_t af[4][4], bb[2][4];
#pragma unroll
            for (int i = 0; i < 4; ++i)
                ldsm4(af[i], aS + (wm + i * 16 + l16) * A_ST + s * 32 + lh * 16);
#pragma unroll
            for (int j = 0; j < 2; ++j)
                ldsm4t(bb[j], bS + (s * 16 + l16) * B_ST + (wn + j * 16) * 2 + lh * 16);
#pragma unroll
            for (int i = 0; i < 4; ++i)
#pragma unroll
                for (int j = 0; j < 2; ++j) {
                    mma_f16(acc[i][2 * j],     af[i], bb[j]);
                    mma_f16(acc[i][2 * j + 1], af[i], bb[j] + 2);
                }
        }
    }

    const int rr = lane >> 2;
    const int cp = (lane & 3) * 2;
#pragma unroll
    for (int i = 0; i < 4; ++i) {
        const int grow = m0 + wm + i * 16 + rr;
#pragma unroll
        for (int j = 0; j < 4; ++j) {
            const int gcol = n0 + wn + j * 8 + cp;
            float2 bb = *(const float2*)(bias + gcol);
            float x0 = (acc[i][j][0] + bb.x) * scl, y0 = (acc[i][j][1] + bb.y) * scl;
            float x1 = (acc[i][j][2] + bb.x) * scl, y1 = (acc[i][j][3] + bb.y) * scl;
            if constexpr (sizeof(OutT) == 2) {
                *(__half2*)((__half*)C + (size_t)grow * EMB + gcol)       = __floats2half2_rn(x0, y0);
                *(__half2*)((__half*)C + (size_t)(grow + 8) * EMB + gcol) = __floats2half2_rn(x1, y1);
            } else {
                *(float2*)((float*)C + (size_t)grow * EMB + gcol)       = make_float2(x0, y0);
                *(float2*)((float*)C + (size_t)(grow + 8) * EMB + gcol) = make_float2(x1, y1);
            }
        }
    }
}

// ---------------- split-KV fp16 flash attention, 32 q-rows/warp ----------------
// block 128 threads, Q tile 128 (warp w: rows w*32..w*32+31, two a-frag sets),
// KV tile 64 double-buffered. Each K/V ldmatrix feeds 2x HMMA (register reuse).
// grid (80, HEADS): (qt in 128-rows, chunk of 16 KV tiles), largest chains first.
#define ATT_SMEM (3 * 128 * 128)     // Q 16KB + K 2x8KB + V 2x8KB
#define NEG_BIG (-1e30f)

__global__ __launch_bounds__(128) void attn_part(
    const __half* __restrict__ Q, const __half* __restrict__ K,
    const __half* __restrict__ V, __half* __restrict__ OP, float* __restrict__ LP)
{
    extern __shared__ __half smh[];
    const uint32_t qB = smem_u32(smh);
    const uint32_t kB = qB + 16384;
    const uint32_t vB = kB + 16384;

    // decode (qt, c): qt has 2*qt+2 KV tiles, chunks of 16; largest first
    int idx = blockIdx.x, qt, c;
    if (idx < 32)      { qt = 31 - (idx >> 2); c = idx & 3; }
    else if (idx < 56) { int r = idx - 32; qt = 23 - r / 3; c = r % 3; }
    else if (idx < 72) { int r = idx - 56; qt = 15 - (r >> 1); c = r & 1; }
    else               { qt = 7 - (idx - 72); c = 0; }

    const int tid  = threadIdx.x;
    const int wid  = tid >> 5;
    const int lane = tid & 31;
    const int lg   = lane >> 2;
    const int lc   = lane & 3;
    const int lr   = lane & 7;
    const int g    = lane >> 3;
    const int h    = blockIdx.y;

    const int krow_off = (g >> 1) * 8 + lr;
    const int vrow_off = (g & 1) * 8 + lr;

    const int q0 = qt * 128;
    const int t0 = c * 16;
    const int t1 = min(2 * qt + 1, t0 + 15);

    // stage Q tile (128 x 64)
    {
        const __half* Qg = Q + (size_t)q0 * EMB + h * HD;
#pragma unroll
        for (int i = 0; i < 8; ++i) {
            int f = i * 128 + tid;
            int row = f >> 3, cc = f & 7;
            cpa16(qB + row * 128 + ((cc ^ (row & 7)) * 16), Qg + (size_t)row * EMB + cc * 8);
        }
        CP_COMMIT();
    }
    auto stageKV = [&](int t) {
        const int st = (t & 1) * 8192;
        const __half* Kg = K + (size_t)(t * 64) * EMB + h * HD;
        const __half* Vg = V + (size_t)(t * 64) * EMB + h * HD;
#pragma unroll
        for (int i = 0; i < 4; ++i) {
            int f = i * 128 + tid;
            int row = f >> 3, cc = f & 7;
            int off = row * 128 + ((cc ^ (row & 7)) * 16);
            cpa16(kB + st + off, Kg + (size_t)row * EMB + cc * 8);
            cpa16(vB + st + off, Vg + (size_t)row * EMB + cc * 8);
        }
        CP_COMMIT();
    };

    stageKV(t0);
    CP_WAIT(1);
    __syncthreads();

    // Q fragments: two row-sets per warp
    uint32_t qf[2][4][4];
#pragma unroll
    for (int u = 0; u < 2; ++u) {
        const int qrow = wid * 32 + u * 16 + (g & 1) * 8 + lr;
#pragma unroll
        for (int kf = 0; kf < 4; ++kf)
            ldsm4(qf[u][kf], qB + qrow * 128 + (((2 * kf + (g >> 1)) ^ lr) * 16));
    }

    float o[2][8][4];
#pragma unroll
    for (int u = 0; u < 2; ++u)
#pragma unroll
        for (int nf = 0; nf < 8; ++nf)
#pragma unroll
            for (int j = 0; j < 4; ++j) o[u][nf][j] = 0.f;
    float lacc[2][4] = {{0.f, 0.f, 0.f, 0.f}, {0.f, 0.f, 0.f, 0.f}};
    const uint32_t ONES2 = 0x3C003C00u;
    const uint32_t ones_b[2] = {ONES2, ONES2};

#pragma unroll 1
    for (int t = t0; t <= t1; ++t) {
        if (t + 1 <= t1) { stageKV(t + 1); CP_WAIT(1); }
        else             { CP_WAIT(0); }
        __syncthreads();

        const uint32_t kS = kB + (t & 1) * 8192;
        const uint32_t vS = vB + (t & 1) * 8192;

        // ---- S = Q @ K^T : each K b-frag feeds both q-sets ----
        float s[2][8][4];
#pragma unroll
        for (int u = 0; u < 2; ++u)
#pragma unroll
            for (int nf = 0; nf < 8; ++nf)
#pragma unroll
                for (int j = 0; j < 4; ++j) s[u][nf][j] = 0.f;
#pragma unroll
        for (int kf = 0; kf < 4; ++kf) {
#pragma unroll
            for (int nfp = 0; nfp < 4; ++nfp) {
                uint32_t kb4[4];
                ldsm4(kb4, kS + (nfp * 16 + krow_off) * 128 +
                           (((2 * kf + (g & 1)) ^ lr) * 16));
#pragma unroll
                for (int u = 0; u < 2; ++u) {
                    mma_f16(s[u][2 * nfp],     qf[u][kf], kb4);
                    mma_f16(s[u][2 * nfp + 1], qf[u][kf], kb4 + 2);
                }
            }
        }

        // ---- causal mask (diagonal tiles: t >= 2*qt) ----
        if (t >= 2 * qt) {
            const int kb0 = t * 64;
#pragma unroll
            for (int u = 0; u < 2; ++u) {
                const int qg = q0 + wid * 32 + u * 16 + lg;
#pragma unroll
                for (int nf = 0; nf < 8; ++nf) {
                    const int kv0 = kb0 + nf * 8 + 2 * lc;
                    if (kv0     > qg)     s[u][nf][0] = NEG_BIG;
                    if (kv0 + 1 > qg)     s[u][nf][1] = NEG_BIG;
                    if (kv0     > qg + 8) s[u][nf][2] = NEG_BIG;
                    if (kv0 + 1 > qg + 8) s[u][nf][3] = NEG_BIG;
                }
            }
        }

        // ---- p = 2^s (fp16x2) ----
        uint32_t pe[2][8][2];
#pragma unroll
        for (int u = 0; u < 2; ++u)
#pragma unroll
            for (int nf = 0; nf < 8; ++nf) {
                pe[u][nf][0] = ex2h2(s[u][nf][0], s[u][nf][1]);
                pe[u][nf][1] = ex2h2(s[u][nf][2], s[u][nf][3]);
            }

        // ---- O += P @ V, l += P @ ones : each V b-frag feeds both q-sets ----
#pragma unroll
        for (int kf = 0; kf < 4; ++kf) {
            uint32_t pa[2][4];
#pragma unroll
            for (int u = 0; u < 2; ++u) {
                pa[u][0] = pe[u][2 * kf][0];
                pa[u][1] = pe[u][2 * kf][1];
                pa[u][2] = pe[u][2 * kf + 1][0];
                pa[u][3] = pe[u][2 * kf + 1][1];
                mma_f16(lacc[u], pa[u], ones_b);
            }
#pragma unroll
            for (int nfp = 0; nfp < 4; ++nfp) {
                uint32_t vb4[4];
                ldsm4t(vb4, vS + (kf * 16 + vrow_off) * 128 +
                            (((2 * nfp + (g >> 1)) ^ lr) * 16));
#pragma unroll
                for (int u = 0; u < 2; ++u) {
                    mma_f16(o[u][2 * nfp],     pa[u], vb4);
                    mma_f16(o[u][2 * nfp + 1], pa[u], vb4 + 2);
                }
            }
        }
        __syncthreads();
    }

    // ---- write partial: O (fp16, 128x64 row-major) + l (fp32) ----
    const int pbase = ((h * 32 + qt) * 4 + c);
    __half* op = OP + (size_t)pbase * 8192;
#pragma unroll
    for (int u = 0; u < 2; ++u) {
        const int r0 = wid * 32 + u * 16 + lg;
#pragma unroll
        for (int nf = 0; nf < 8; ++nf) {
            *(__half2*)(op + r0 * 64 + nf * 8 + 2 * lc)       = __floats2half2_rn(o[u][nf][0], o[u][nf][1]);
            *(__half2*)(op + (r0 + 8) * 64 + nf * 8 + 2 * lc) = __floats2half2_rn(o[u][nf][2], o[u][nf][3]);
        }
        if (lc == 0) {
            LP[pbase * 128 + r0]     = lacc[u][0];
            LP[pbase * 128 + r0 + 8] = lacc[u][2];
        }
    }
}

// ---------------- combine: CTX = (sum_c O_c) / (sum_c l_c) ----------------
__global__ __launch_bounds__(256) void attn_combine(
    const __half* __restrict__ OP, const float* __restrict__ LP,
    __half* __restrict__ CTX)
{
    const int qt = blockIdx.x;            // 0..31 (128 rows each)
    const int h  = blockIdx.y;
    const int nc = (2 * qt + 2 + 15) / 16;
    const int tid = threadIdx.x;
    const int row = tid >> 1;             // 0..127
    const int cb  = (tid & 1) * 32;

    float acc[32];
#pragma unroll
    for (int i = 0; i < 32; ++i) acc[i] = 0.f;
    float lsum = 0.f;

#pragma unroll 1
    for (int c = 0; c < nc; ++c) {
        const int pbase = ((h * 32 + qt) * 4 + c);
        lsum += LP[pbase * 128 + row];
        const __half* op = OP + (size_t)pbase * 8192 + row * 64 + cb;
#pragma unroll
        for (int u = 0; u < 4; ++u) {
            uint4 v = *(const uint4*)(op + u * 8);
            const __half2* hp = (const __half2*)&v;
#pragma unroll
            for (int k = 0; k < 4; ++k) {
                float2 f = __half22float2(hp[k]);
                acc[u * 8 + 2 * k]     += f.x;
                acc[u * 8 + 2 * k + 1] += f.y;
            }
        }
    }

    const float inv = 1.f / lsum;
    __half2 outp[16];
#pragma unroll
    for (int k = 0; k < 16; ++k)
        outp[k] = __floats2half2_rn(acc[2 * k] * inv, acc[2 * k + 1] * inv);
    __half* dst = CTX + (size_t)(qt * 128 + row) * EMB + h * HD + cb;
#pragma unroll
    for (int u = 0; u < 4; ++u)
        *(uint4*)(dst + u * 8) = ((uint4*)outp)[u];
}

// ---------------- launch ----------------
extern "C" void kernel_launch(void* const* d_in, const int* in_sizes, int n_in,
                              void* d_out, int out_size)
{
    const float* x  = (const float*)d_in[0];
    const float* wq = (const float*)d_in[1];
    const float* bq = (const float*)d_in[2];
    const float* wk = (const float*)d_in[3];
    const float* bk = (const float*)d_in[4];
    const float* wv = (const float*)d_in[5];
    const float* bv = (const float*)d_in[6];
    const float* wo = (const float*)d_in[7];
    const float* bo = (const float*)d_in[8];
    float* out = (float*)d_out;

    __half *Xp, *Wp, *Qp, *Kp, *Vp, *Cp, *OPp;
    float *LPp;
    cudaGetSymbolAddress((void**)&Xp, g_X);
    cudaGetSymbolAddress((void**)&Wp, g_W);
    cudaGetSymbolAddress((void**)&Qp, g_Q);
    cudaGetSymbolAddress((void**)&Kp, g_K);
    cudaGetSymbolAddress((void**)&Vp, g_V);
    cudaGetSymbolAddress((void**)&Cp, g_CTX);
    cudaGetSymbolAddress((void**)&OPp, g_OP);
    cudaGetSymbolAddress((void**)&LPp, g_LP);

    __half* wqh = Wp + 0 * EMB * EMB;
    __half* wkh = Wp + 1 * EMB * EMB;
    __half* wvh = Wp + 2 * EMB * EMB;
    __half* woh = Wp + 3 * EMB * EMB;

    static bool attr_set = false;
    if (!attr_set) {
        cudaFuncSetAttribute(attn_part, cudaFuncAttributeMaxDynamicSharedMemorySize, ATT_SMEM);
        cudaFuncSetAttribute(gemm_h<__half>, cudaFuncAttributeMaxDynamicSharedMemorySize, GEMM_SMEM);
        cudaFuncSetAttribute(gemm_h<float>,  cudaFuncAttributeMaxDynamicSharedMemorySize, GEMM_SMEM);
        attr_set = true;
    }

    f2h_kernel<<<SEQ * EMB / 2048, 256>>>(x, Xp);
    dim3 wgrid(EMB * EMB / 2048, 4);
    f2h_w4<<<wgrid, 256>>>(wq, wk, wv, wo, Wp);

    const float QS = 0.125f * 1.44269504f;
    dim3 qkv_grid(EMB / 128, SEQ / 128, 3);
    gemm_h<__half><<<qkv_grid, 256, GEMM_SMEM>>>(Xp, wqh, wkh, wvh, bq, bk, bv,
                                                 Qp, Kp, Vp, QS, 1.f, 1.f);

    dim3 agrid(80, HEADS);
    attn_part<<<agrid, 128, ATT_SMEM>>>(Qp, Kp, Vp, OPp, LPp);
    dim3 cgrid(32, HEADS);
    attn_combine<<<cgrid, 256>>>(OPp, LPp, Cp);

    dim3 ogrid(EMB / 128, SEQ / 128, 1);
    gemm_h<float><<<ogrid, 256, GEMM_SMEM>>>(Cp, woh, woh, woh, bo, bo, bo,
                                             out, out, out, 1.f, 1.f, 1.f);
}

// round 11
// speedup vs baseline: 1.0272x; 1.0272x over previous
#include <cuda_runtime.h>
#include <cuda_fp16.h>
#include <cstdint>
#include <math.h>

#define SEQ   4096
#define EMB   768
#define HEADS 12
#define HD    64

// ---------------- scratch (static device globals, no runtime alloc) ----------------
__device__ __half g_X[SEQ * EMB];
__device__ __half g_W[4][EMB * EMB];
__device__ __half g_Q[SEQ * EMB];
__device__ __half g_K[SEQ * EMB];
__device__ __half g_V[SEQ * EMB];
__device__ __half g_CTX[SEQ * EMB];
// split-KV partials: [head][qt(64)][chunk(4)] -> O 64x64 fp16, l 64 fp32
__device__ __half g_OP[HEADS * 64 * 4 * 64 * 64];
__device__ float  g_LP[HEADS * 64 * 4 * 64];

// ======================= helpers =======================
__device__ __forceinline__ void mma_f16(float* d, const uint32_t* a, const uint32_t* b) {
    asm volatile(
        "mma.sync.aligned.m16n8k16.row.col.f32.f16.f16.f32 "
        "{%0,%1,%2,%3}, {%4,%5,%6,%7}, {%8,%9}, {%0,%1,%2,%3};"
        : "+f"(d[0]), "+f"(d[1]), "+f"(d[2]), "+f"(d[3])
        : "r"(a[0]), "r"(a[1]), "r"(a[2]), "r"(a[3]), "r"(b[0]), "r"(b[1]));
}
__device__ __forceinline__ void ldsm4(uint32_t* r, uint32_t a) {
    asm volatile("ldmatrix.sync.aligned.m8n8.x4.shared.b16 {%0,%1,%2,%3}, [%4];"
        : "=r"(r[0]), "=r"(r[1]), "=r"(r[2]), "=r"(r[3]) : "r"(a));
}
__device__ __forceinline__ void ldsm4t(uint32_t* r, uint32_t a) {
    asm volatile("ldmatrix.sync.aligned.m8n8.x4.trans.shared.b16 {%0,%1,%2,%3}, [%4];"
        : "=r"(r[0]), "=r"(r[1]), "=r"(r[2]), "=r"(r[3]) : "r"(a));
}
__device__ __forceinline__ uint32_t ex2h2(float x, float y) {
    __half2 h = __floats2half2_rn(x, y);
    uint32_t u = *(uint32_t*)&h, r;
    asm("ex2.approx.f16x2 %0, %1;" : "=r"(r) : "r"(u));
    return r;
}
__device__ __forceinline__ uint32_t smem_u32(const void* p) {
    uint32_t a;
    asm("{ .reg .u64 t; cvta.to.shared.u64 t, %1; cvt.u32.u64 %0, t; }" : "=r"(a) : "l"(p));
    return a;
}
__device__ __forceinline__ void cpa16(uint32_t dst, const void* src) {
    asm volatile("cp.async.cg.shared.global [%0], [%1], 16;" :: "r"(dst), "l"(src));
}
#define CP_COMMIT() asm volatile("cp.async.commit_group;" ::: "memory")
#define CP_WAIT(n)  asm volatile("cp.async.wait_group %0;" :: "n"(n) : "memory")
#define CP_WAIT_DYN(cond) do { if (cond) CP_WAIT(1); else CP_WAIT(0); } while (0)

// ---------------- fused fp32 -> fp16 converts (x + 4 weights, one launch) ----------------
#define XBLK (SEQ * EMB / 2048)        // 1536
#define WBLK (EMB * EMB / 2048)        // 288
__global__ __launch_bounds__(256) void f2h_all(const float* __restrict__ x,
                                               const float* __restrict__ w0,
                                               const float* __restrict__ w1,
                                               const float* __restrict__ w2,
                                               const float* __restrict__ w3,
                                               __half* __restrict__ X,
                                               __half* __restrict__ W) {
    int idx = blockIdx.x;
    const float* in;
    __half* out;
    int base;
    if (idx < XBLK) { in = x; out = X; base = idx; }
    else {
        int r = idx - XBLK;
        int w = r / WBLK;
        base = r - w * WBLK;
        in = w == 0 ? w0 : (w == 1 ? w1 : (w == 2 ? w2 : w3));
        out = W + (size_t)w * EMB * EMB;
    }
    const int i = (base * 256 + threadIdx.x) * 8;
    float4 a = *(const float4*)(in + i);
    float4 b = *(const float4*)(in + i + 4);
    __half2 h[4] = { __floats2half2_rn(a.x, a.y), __floats2half2_rn(a.z, a.w),
                     __floats2half2_rn(b.x, b.y), __floats2half2_rn(b.z, b.w) };
    *(uint4*)(out + i) = *(uint4*)h;
}

// ---------------- fp16 GEMM (R7-validated) ----------------
#define BK2 32
#define NKT2 (EMB / BK2)
#define STG2 4
#define A_ST 80
#define B_ST 272
#define A_TB (128 * A_ST)
#define B_TB (32 * B_ST)
#define GEMM_SMEM (STG2 * (A_TB + B_TB))

template <typename OutT>
__global__ __launch_bounds__(256, 2) void gemm_h(const __half* __restrict__ A,
                                                 const __half* __restrict__ B0,
                                                 const __half* __restrict__ B1,
                                                 const __half* __restrict__ B2,
                                                 const float* __restrict__ bias0,
                                                 const float* __restrict__ bias1,
                                                 const float* __restrict__ bias2,
                                                 OutT* __restrict__ C0,
                                                 OutT* __restrict__ C1,
                                                 OutT* __restrict__ C2,
                                                 float sc0, float sc1, float sc2) {
    extern __shared__ char gsm[];
    const uint32_t sA = smem_u32(gsm);
    const uint32_t sB = sA + STG2 * A_TB;

    const int z = blockIdx.z;
    const __half* B   = z == 0 ? B0 : (z == 1 ? B1 : B2);
    const float* bias = z == 0 ? bias0 : (z == 1 ? bias1 : bias2);
    OutT* C           = z == 0 ? C0 : (z == 1 ? C1 : C2);
    const float scl   = z == 0 ? sc0 : (z == 1 ? sc1 : sc2);

    const int tid  = threadIdx.x;
    const int wid  = tid >> 5;
    const int lane = tid & 31;
    const int l16  = lane & 15;
    const int lh   = lane >> 4;
    const int wm   = (wid >> 2) * 64;
    const int wn   = (wid & 3) * 32;
    const int m0   = blockIdx.y * 128;
    const int n0   = blockIdx.x * 128;

    auto issue = [&](int kt) {
        const int st = kt & 3;
#pragma unroll
        for (int i = 0; i < 2; ++i) {
            int f = i * 256 + tid;
            int row = f >> 2, c = f & 3;
            cpa16(sA + st * A_TB + row * A_ST + c * 16,
                  A + (size_t)(m0 + row) * EMB + kt * BK2 + c * 8);
        }
#pragma unroll
        for (int i = 0; i < 2; ++i) {
            int f = i * 256 + tid;
            int row = f >> 4, c = f & 15;
            cpa16(sB + st * B_TB + row * B_ST + c * 16,
                  B + (size_t)(kt * BK2 + row) * EMB + n0 + c * 8);
        }
        CP_COMMIT();
    };

    float acc[4][4][4];
#pragma unroll
    for (int i = 0; i < 4; ++i)
#pragma unroll
        for (int j = 0; j < 4; ++j)
#pragma unroll
            for (int k = 0; k < 4; ++k) acc[i][j][k] = 0.f;

    issue(0); issue(1); issue(2);

#pragma unroll 1
    for (int kt = 0; kt < NKT2; ++kt) {
        CP_WAIT(2);
        __syncthreads();
        if (kt + 3 < NKT2) issue(kt + 3);
        else CP_COMMIT();

        const uint32_t aS = sA + (kt & 3) * A_TB;
        const uint32_t bS = sB + (kt & 3) * B_TB;

#pragma unroll
        for (int s = 0; s < 2; ++s) {
            uint32_t af[4][4], bb[2][4];
#pragma unroll
            for (int i = 0; i < 4; ++i)
                ldsm4(af[i], aS + (wm + i * 16 + l16) * A_ST + s * 32 + lh * 16);
#pragma unroll
            for (int j = 0; j < 2; ++j)
                ldsm4t(bb[j], bS + (s * 16 + l16) * B_ST + (wn + j * 16) * 2 + lh * 16);
#pragma unroll
            for (int i = 0; i < 4; ++i)
#pragma unroll
                for (int j = 0; j < 2; ++j) {
                    mma_f16(acc[i][2 * j],     af[i], bb[j]);
                    mma_f16(acc[i][2 * j + 1], af[i], bb[j] + 2);
                }
        }
    }

    const int rr = lane >> 2;
    const int cp = (lane & 3) * 2;
#pragma unroll
    for (int i = 0; i < 4; ++i) {
        const int grow = m0 + wm + i * 16 + rr;
#pragma unroll
        for (int j = 0; j < 4; ++j) {
            const int gcol = n0 + wn + j * 8 + cp;
            float2 bb = *(const float2*)(bias + gcol);
            float x0 = (acc[i][j][0] + bb.x) * scl, y0 = (acc[i][j][1] + bb.y) * scl;
            float x1 = (acc[i][j][2] + bb.x) * scl, y1 = (acc[i][j][3] + bb.y) * scl;
            if constexpr (sizeof(OutT) == 2) {
                *(__half2*)((__half*)C + (size_t)grow * EMB + gcol)       = __floats2half2_rn(x0, y0);
                *(__half2*)((__half*)C + (size_t)(grow + 8) * EMB + gcol) = __floats2half2_rn(x1, y1);
            } else {
                *(float2*)((float*)C + (size_t)grow * EMB + gcol)       = make_float2(x0, y0);
                *(float2*)((float*)C + (size_t)(grow + 8) * EMB + gcol) = make_float2(x1, y1);
            }
        }
    }
}

// ---------------- split-KV fp16 flash attention, 3-stage ring, 1 barrier/tile ----------------
// block 128 threads (4 warps x 16 q-rows), Q tile 64, KV tile 64, chunks of <=16 tiles.
// grid (160, HEADS), largest chains first. Single __syncthreads per tile so warps
// decorrelate across MMA/exp phases (fills the tensor pipe).
#define ATT_SMEM (8192 + 3 * 8192 + 3 * 8192)   // Q + K ring + V ring = 57344
#define NEG_BIG (-1e30f)

__global__ __launch_bounds__(128) void attn_part(
    const __half* __restrict__ Q, const __half* __restrict__ K,
    const __half* __restrict__ V, __half* __restrict__ OP, float* __restrict__ LP)
{
    extern __shared__ __half smh[];
    const uint32_t qB = smem_u32(smh);
    const uint32_t kB = qB + 8192;
    const uint32_t vB = kB + 24576;

    // decode (qt, c), largest chains first
    int idx = blockIdx.x, qt, c;
    if (idx < 64)       { qt = 63 - (idx >> 2); c = idx & 3; }
    else if (idx < 112) { int r = idx - 64;  qt = 47 - r / 3; c = r % 3; }
    else if (idx < 144) { int r = idx - 112; qt = 31 - (r >> 1); c = r & 1; }
    else                { qt = 15 - (idx - 144); c = 0; }

    const int tid  = threadIdx.x;
    const int wid  = tid >> 5;
    const int lane = tid & 31;
    const int lg   = lane >> 2;
    const int lc   = lane & 3;
    const int lr   = lane & 7;
    const int g    = lane >> 3;
    const int h    = blockIdx.y;

    const int qrow     = wid * 16 + (g & 1) * 8 + lr;
    const int krow_off = (g >> 1) * 8 + lr;
    const int vrow_off = (g & 1) * 8 + lr;

    const int q0 = qt * 64;
    const int t0 = c * 16;
    const int t1 = min(qt, t0 + 15);

    // stage Q (group 0)
    {
        const __half* Qg = Q + (size_t)q0 * EMB + h * HD;
#pragma unroll
        for (int i = 0; i < 4; ++i) {
            int f = i * 128 + tid;
            int row = f >> 3, cc = f & 7;
            cpa16(qB + row * 128 + ((cc ^ (row & 7)) * 16), Qg + (size_t)row * EMB + cc * 8);
        }
        CP_COMMIT();
    }
    auto stageKV = [&](int t) {
        const int st = (t % 3) * 8192;
        const __half* Kg = K + (size_t)(t * 64) * EMB + h * HD;
        const __half* Vg = V + (size_t)(t * 64) * EMB + h * HD;
#pragma unroll
        for (int i = 0; i < 4; ++i) {
            int f = i * 128 + tid;
            int row = f >> 3, cc = f & 7;
            int off = row * 128 + ((cc ^ (row & 7)) * 16);
            cpa16(kB + st + off, Kg + (size_t)row * EMB + cc * 8);
            cpa16(vB + st + off, Vg + (size_t)row * EMB + cc * 8);
        }
        CP_COMMIT();
    };

    stageKV(t0);
    if (t0 + 1 <= t1) stageKV(t0 + 1);

    uint32_t qf[4][4];
    float o[8][4];
#pragma unroll
    for (int nf = 0; nf < 8; ++nf)
#pragma unroll
        for (int j = 0; j < 4; ++j) o[nf][j] = 0.f;
    float lacc[4] = {0.f, 0.f, 0.f, 0.f};
    const uint32_t ONES2 = 0x3C003C00u;
    const uint32_t ones_b[2] = {ONES2, ONES2};

    const int qr  = wid * 16 + lg;
    const int qg0 = q0 + qr;

#pragma unroll 1
    for (int t = t0; t <= t1; ++t) {
        // tile t complete (leave the newest group in flight)
        CP_WAIT_DYN(t < t1);
        __syncthreads();                 // ONLY barrier this tile
        if (t + 2 <= t1) stageKV(t + 2); // overwrites buffer (t-1)%3: all warps past barrier => done reading it

        if (t == t0) {
#pragma unroll
            for (int kf = 0; kf < 4; ++kf)
                ldsm4(qf[kf], qB + qrow * 128 + (((2 * kf + (g >> 1)) ^ lr) * 16));
        }

        const uint32_t kS = kB + (t % 3) * 8192;
        const uint32_t vS = vB + (t % 3) * 8192;

        // ---- S = Q @ K^T ----
        float s[8][4];
#pragma unroll
        for (int nf = 0; nf < 8; ++nf)
#pragma unroll
            for (int j = 0; j < 4; ++j) s[nf][j] = 0.f;
#pragma unroll
        for (int kf = 0; kf < 4; ++kf) {
#pragma unroll
            for (int nfp = 0; nfp < 4; ++nfp) {
                uint32_t kb4[4];
                ldsm4(kb4, kS + (nfp * 16 + krow_off) * 128 +
                           (((2 * kf + (g & 1)) ^ lr) * 16));
                mma_f16(s[2 * nfp],     qf[kf], kb4);
                mma_f16(s[2 * nfp + 1], qf[kf], kb4 + 2);
            }
        }

        // ---- causal mask (diagonal tile only) ----
        if (t == qt) {
            const int kb0 = t * 64;
#pragma unroll
            for (int nf = 0; nf < 8; ++nf) {
                const int kv0 = kb0 + nf * 8 + 2 * lc;
                if (kv0     > qg0)     s[nf][0] = NEG_BIG;
                if (kv0 + 1 > qg0)     s[nf][1] = NEG_BIG;
                if (kv0     > qg0 + 8) s[nf][2] = NEG_BIG;
                if (kv0 + 1 > qg0 + 8) s[nf][3] = NEG_BIG;
            }
        }

        // ---- p = 2^s (fp16x2) ----
        uint32_t pe[8][2];
#pragma unroll
        for (int nf = 0; nf < 8; ++nf) {
            pe[nf][0] = ex2h2(s[nf][0], s[nf][1]);
            pe[nf][1] = ex2h2(s[nf][2], s[nf][3]);
        }

        // ---- O += P @ V, l += P @ ones ----
#pragma unroll
        for (int kf = 0; kf < 4; ++kf) {
            uint32_t pa[4];
            pa[0] = pe[2 * kf][0];
            pa[1] = pe[2 * kf][1];
            pa[2] = pe[2 * kf + 1][0];
            pa[3] = pe[2 * kf + 1][1];
            mma_f16(lacc, pa, ones_b);
#pragma unroll
            for (int nfp = 0; nfp < 4; ++nfp) {
                uint32_t vb4[4];
                ldsm4t(vb4, vS + (kf * 16 + vrow_off) * 128 +
                            (((2 * nfp + (g >> 1)) ^ lr) * 16));
                mma_f16(o[2 * nfp],     pa, vb4);
                mma_f16(o[2 * nfp + 1], pa, vb4 + 2);
            }
        }
        // no trailing barrier
    }

    // ---- write partial: O (fp16, row-major 64x64) + l (fp32) ----
    const int pbase = ((h * 64 + qt) * 4 + c);
    __half* op = OP + (size_t)pbase * 4096;
#pragma unroll
    for (int nf = 0; nf < 8; ++nf) {
        *(__half2*)(op + qr * 64 + nf * 8 + 2 * lc)       = __floats2half2_rn(o[nf][0], o[nf][1]);
        *(__half2*)(op + (qr + 8) * 64 + nf * 8 + 2 * lc) = __floats2half2_rn(o[nf][2], o[nf][3]);
    }
    if (lc == 0) {
        LP[pbase * 64 + qr]     = lacc[0];
        LP[pbase * 64 + qr + 8] = lacc[2];
    }
}

// ---------------- combine: CTX = (sum_c O_c) / (sum_c l_c) ----------------
__global__ __launch_bounds__(128) void attn_combine(
    const __half* __restrict__ OP, const float* __restrict__ LP,
    __half* __restrict__ CTX)
{
    const int qt = blockIdx.x;
    const int h  = blockIdx.y;
    const int nc = (qt >> 4) + 1;
    const int tid = threadIdx.x;
    const int row = tid >> 1;
    const int cb  = (tid & 1) * 32;

    float acc[32];
#pragma unroll
    for (int i = 0; i < 32; ++i) acc[i] = 0.f;
    float lsum = 0.f;

#pragma unroll 1
    for (int c = 0; c < nc; ++c) {
        const int pbase = ((h * 64 + qt) * 4 + c);
        lsum += LP[pbase * 64 + row];
        const __half* op = OP + (size_t)pbase * 4096 + row * 64 + cb;
#pragma unroll
        for (int u = 0; u < 4; ++u) {
            uint4 v = *(const uint4*)(op + u * 8);
            const __half2* hp = (const __half2*)&v;
#pragma unroll
            for (int k = 0; k < 4; ++k) {
                float2 f = __half22float2(hp[k]);
                acc[u * 8 + 2 * k]     += f.x;
                acc[u * 8 + 2 * k + 1] += f.y;
            }
        }
    }

    const float inv = 1.f / lsum;
    __half2 outp[16];
#pragma unroll
    for (int k = 0; k < 16; ++k)
        outp[k] = __floats2half2_rn(acc[2 * k] * inv, acc[2 * k + 1] * inv);
    __half* dst = CTX + (size_t)(qt * 64 + row) * EMB + h * HD + cb;
#pragma unroll
    for (int u = 0; u < 4; ++u)
        *(uint4*)(dst + u * 8) = ((uint4*)outp)[u];
}

// ---------------- launch ----------------
extern "C" void kernel_launch(void* const* d_in, const int* in_sizes, int n_in,
                              void* d_out, int out_size)
{
    const float* x  = (const float*)d_in[0];
    const float* wq = (const float*)d_in[1];
    const float* bq = (const float*)d_in[2];
    const float* wk = (const float*)d_in[3];
    const float* bk = (const float*)d_in[4];
    const float* wv = (const float*)d_in[5];
    const float* bv = (const float*)d_in[6];
    const float* wo = (const float*)d_in[7];
    const float* bo = (const float*)d_in[8];
    float* out = (float*)d_out;

    __half *Xp, *Wp, *Qp, *Kp, *Vp, *Cp, *OPp;
    float *LPp;
    cudaGetSymbolAddress((void**)&Xp, g_X);
    cudaGetSymbolAddress((void**)&Wp, g_W);
    cudaGetSymbolAddress((void**)&Qp, g_Q);
    cudaGetSymbolAddress((void**)&Kp, g_K);
    cudaGetSymbolAddress((void**)&Vp, g_V);
    cudaGetSymbolAddress((void**)&Cp, g_CTX);
    cudaGetSymbolAddress((void**)&OPp, g_OP);
    cudaGetSymbolAddress((void**)&LPp, g_LP);

    __half* wqh = Wp + 0 * EMB * EMB;
    __half* wkh = Wp + 1 * EMB * EMB;
    __half* wvh = Wp + 2 * EMB * EMB;
    __half* woh = Wp + 3 * EMB * EMB;

    static bool attr_set = false;
    if (!attr_set) {
        cudaFuncSetAttribute(attn_part, cudaFuncAttributeMaxDynamicSharedMemorySize, ATT_SMEM);
        cudaFuncSetAttribute(gemm_h<__half>, cudaFuncAttributeMaxDynamicSharedMemorySize, GEMM_SMEM);
        cudaFuncSetAttribute(gemm_h<float>,  cudaFuncAttributeMaxDynamicSharedMemorySize, GEMM_SMEM);
        attr_set = true;
    }

    // fused converts (x + 4 weights, single launch)
    f2h_all<<<XBLK + 4 * WBLK, 256>>>(x, wq, wk, wv, wo, Xp, Wp);

    const float QS = 0.125f * 1.44269504f;
    dim3 qkv_grid(EMB / 128, SEQ / 128, 3);
    gemm_h<__half><<<qkv_grid, 256, GEMM_SMEM>>>(Xp, wqh, wkh, wvh, bq, bk, bv,
                                                 Qp, Kp, Vp, QS, 1.f, 1.f);

    dim3 agrid(160, HEADS);
    attn_part<<<agrid, 128, ATT_SMEM>>>(Qp, Kp, Vp, OPp, LPp);
    dim3 cgrid(64, HEADS);
    attn_combine<<<cgrid, 128>>>(OPp, LPp, Cp);

    dim3 ogrid(EMB / 128, SEQ / 128, 1);
    gemm_h<float><<<ogrid, 256, GEMM_SMEM>>>(Cp, woh, woh, woh, bo, bo, bo,
                                             out, out, out, 1.f, 1.f, 1.f);
}